// round 1
// baseline (speedup 1.0000x reference)
#include <cuda_runtime.h>

// Problem constants
constexpr int NNODES = 100000;   // N_USERS + N_ITEMS
constexpr int D      = 64;       // DIM
constexpr int NE     = 1250000;  // N_EDGES
// BN_EPS = 1e-5

// ---------------------------------------------------------------------------
// Device scratch (no allocation allowed in kernel_launch)
// ---------------------------------------------------------------------------
__device__ float  g_h[NNODES * D];      // h' = dis[n] * (x @ W^T)[n]
__device__ float  g_x[NNODES * D];      // current node features between layers
__device__ float  g_dis[NNODES];        // deg^{-1/2} (deg includes self loop)
__device__ int    g_cnt[NNODES];        // per-dst edge counts (edge list only)
__device__ int    g_rowptr[NNODES + 1]; // CSR row pointers
__device__ int    g_cursor[NNODES];     // CSR fill cursors
__device__ int    g_colidx[NE];         // CSR column (src) indices
__device__ double g_sum[D];
__device__ double g_sumsq[D];
__device__ float  g_scale[D];
__device__ float  g_shift[D];
__device__ int    g_is64;               // edge_index dtype flag

// ---------------------------------------------------------------------------
// 0. zero counters / BN accumulators
// ---------------------------------------------------------------------------
__global__ void k_zero() {
    int i = blockIdx.x * blockDim.x + threadIdx.x;
    if (i < NNODES) g_cnt[i] = 0;
    if (i < D) { g_sum[i] = 0.0; g_sumsq[i] = 0.0; }
}

// ---------------------------------------------------------------------------
// 0b. detect edge_index dtype: int64 (odd 32-bit words all zero) vs int32
// ---------------------------------------------------------------------------
__global__ void k_detect(const int* __restrict__ e) {
    __shared__ int s_nz;
    if (threadIdx.x == 0) s_nz = 0;
    __syncthreads();
    int nz = 0;
    for (int i = threadIdx.x; i < 2048; i += blockDim.x)
        nz |= (e[2 * i + 1] != 0);
    if (nz) atomicOr(&s_nz, 1);
    __syncthreads();
    if (threadIdx.x == 0) g_is64 = (s_nz == 0) ? 1 : 0;
}

// ---------------------------------------------------------------------------
// 1. histogram of dst
// ---------------------------------------------------------------------------
__global__ void k_hist(const void* __restrict__ ep) {
    int i0 = blockIdx.x * blockDim.x + threadIdx.x;
    int stride = gridDim.x * blockDim.x;
    if (g_is64) {
        const long long* e = (const long long*)ep;
        for (int i = i0; i < NE; i += stride)
            atomicAdd(&g_cnt[(int)e[NE + i]], 1);
    } else {
        const int* e = (const int*)ep;
        for (int i = i0; i < NE; i += stride)
            atomicAdd(&g_cnt[e[NE + i]], 1);
    }
}

// ---------------------------------------------------------------------------
// 2. exclusive scan -> rowptr, cursor; also deg_inv_sqrt (deg = cnt + self loop)
//    single block, 1024 threads, chunked Hillis-Steele
// ---------------------------------------------------------------------------
__global__ void __launch_bounds__(1024) k_scan() {
    const int C = (NNODES + 1023) / 1024;  // 98
    int t = threadIdx.x;
    int base = t * C;
    int end  = min(base + C, NNODES);
    int s = 0;
    for (int i = base; i < end; i++) {
        int c = g_cnt[i];
        s += c;
        g_dis[i] = rsqrtf((float)(c + 1));
    }
    __shared__ int sm[1024];
    sm[t] = s;
    __syncthreads();
    for (int off = 1; off < 1024; off <<= 1) {
        int v = (t >= off) ? sm[t - off] : 0;
        __syncthreads();
        sm[t] += v;
        __syncthreads();
    }
    int run = sm[t] - s;  // exclusive prefix
    for (int i = base; i < end; i++) {
        g_rowptr[i] = run;
        g_cursor[i] = run;
        run += g_cnt[i];
    }
    if (t == 1023) g_rowptr[NNODES] = sm[1023];
}

// ---------------------------------------------------------------------------
// 3. CSR fill
// ---------------------------------------------------------------------------
__global__ void k_fill(const void* __restrict__ ep) {
    int i0 = blockIdx.x * blockDim.x + threadIdx.x;
    int stride = gridDim.x * blockDim.x;
    if (g_is64) {
        const long long* e = (const long long*)ep;
        for (int i = i0; i < NE; i += stride) {
            int src = (int)e[i];
            int dst = (int)e[NE + i];
            int p = atomicAdd(&g_cursor[dst], 1);
            g_colidx[p] = src;
        }
    } else {
        const int* e = (const int*)ep;
        for (int i = i0; i < NE; i += stride) {
            int src = e[i];
            int dst = e[NE + i];
            int p = atomicAdd(&g_cursor[dst], 1);
            g_colidx[p] = src;
        }
    }
}

// ---------------------------------------------------------------------------
// 4. GEMM + scale epilogue:  g_h[n] = dis[n] * (X[n] @ W^T)
//    X = Xin if non-null else g_x.  W is [D][D] row-major (W[d][k]).
//    Tile: 128 nodes x 64 dims per block of 256 threads; 4n x 8d per thread.
// ---------------------------------------------------------------------------
__global__ void __launch_bounds__(256) k_gemm(const float* __restrict__ Xin,
                                              const float* __restrict__ W) {
    __shared__ float sx[128 * 64];   // node rows
    __shared__ float sw[64 * 64];    // transposed W: sw[k*64+d] = W[d][k]
    const float* X = Xin ? Xin : g_x;
    int tid = threadIdx.x;

    for (int i = tid; i < 4096; i += 256) {
        int d = i >> 6, k = i & 63;
        sw[k * 64 + d] = W[i];
    }
    int n0 = blockIdx.x * 128;
    const float4* X4 = (const float4*)X;
    float4* sx4 = (float4*)sx;
    for (int i = tid; i < 2048; i += 256) {
        int n = n0 + (i >> 4);
        sx4[i] = (n < NNODES) ? X4[(size_t)n * 16 + (i & 15)]
                              : make_float4(0.f, 0.f, 0.f, 0.f);
    }
    __syncthreads();

    int tc = tid & 7, tr = tid >> 3;
    int d0 = tc * 8;
    int nb = tr * 4;
    float acc[4][8];
#pragma unroll
    for (int i = 0; i < 4; i++)
#pragma unroll
        for (int j = 0; j < 8; j++) acc[i][j] = 0.f;

#pragma unroll 8
    for (int k = 0; k < 64; k++) {
        float4 wa = *(const float4*)&sw[k * 64 + d0];
        float4 wb = *(const float4*)&sw[k * 64 + d0 + 4];
#pragma unroll
        for (int i = 0; i < 4; i++) {
            float xv = sx[(nb + i) * 64 + k];
            acc[i][0] += xv * wa.x; acc[i][1] += xv * wa.y;
            acc[i][2] += xv * wa.z; acc[i][3] += xv * wa.w;
            acc[i][4] += xv * wb.x; acc[i][5] += xv * wb.y;
            acc[i][6] += xv * wb.z; acc[i][7] += xv * wb.w;
        }
    }
#pragma unroll
    for (int i = 0; i < 4; i++) {
        int n = n0 + nb + i;
        if (n < NNODES) {
            float dv = g_dis[n];
            float4 o0 = make_float4(acc[i][0] * dv, acc[i][1] * dv,
                                    acc[i][2] * dv, acc[i][3] * dv);
            float4 o1 = make_float4(acc[i][4] * dv, acc[i][5] * dv,
                                    acc[i][6] * dv, acc[i][7] * dv);
            *(float4*)&g_h[(size_t)n * 64 + d0]     = o0;
            *(float4*)&g_h[(size_t)n * 64 + d0 + 4] = o1;
        }
    }
}

// ---------------------------------------------------------------------------
// 5. Aggregation: warp per node, lane l owns float2 at dim 2l.
//    out[n] = dis[n] * (h'[n] + sum_{src in nbrs(n)} h'[src]) + b
// ---------------------------------------------------------------------------
__global__ void __launch_bounds__(256) k_agg(const float* __restrict__ b) {
    int w = (blockIdx.x * blockDim.x + threadIdx.x) >> 5;
    int l = threadIdx.x & 31;
    if (w >= NNODES) return;
    const float2* __restrict__ h2 = (const float2*)g_h;
    float2 acc = h2[(size_t)w * 32 + l];  // self loop term
    int beg = g_rowptr[w];
    int end = g_rowptr[w + 1];
    int j = beg;
    for (; j + 3 < end; j += 4) {
        int s0 = g_colidx[j], s1 = g_colidx[j + 1];
        int s2 = g_colidx[j + 2], s3 = g_colidx[j + 3];
        float2 a0 = h2[(size_t)s0 * 32 + l];
        float2 a1 = h2[(size_t)s1 * 32 + l];
        float2 a2 = h2[(size_t)s2 * 32 + l];
        float2 a3 = h2[(size_t)s3 * 32 + l];
        acc.x += (a0.x + a1.x) + (a2.x + a3.x);
        acc.y += (a0.y + a1.y) + (a2.y + a3.y);
    }
    for (; j < end; j++) {
        int s = g_colidx[j];
        float2 a = h2[(size_t)s * 32 + l];
        acc.x += a.x; acc.y += a.y;
    }
    float dv = g_dis[w];
    float2 bv = ((const float2*)b)[l];
    float2 r;
    r.x = acc.x * dv + bv.x;
    r.y = acc.y * dv + bv.y;
    ((float2*)g_x)[(size_t)w * 32 + l] = r;
}

// ---------------------------------------------------------------------------
// 6. BN column reduction (double accumulators)
// ---------------------------------------------------------------------------
__global__ void __launch_bounds__(256) k_bnred() {
    int d  = threadIdx.x & 63;
    int r0 = blockIdx.x * 4 + (threadIdx.x >> 6);
    int rs = gridDim.x * 4;
    double s = 0.0, q = 0.0;
    for (int n = r0; n < NNODES; n += rs) {
        double v = (double)g_x[(size_t)n * 64 + d];
        s += v;
        q += v * v;
    }
    __shared__ double ss[256], sq[256];
    ss[threadIdx.x] = s;
    sq[threadIdx.x] = q;
    __syncthreads();
    if (threadIdx.x < 64) {
        s = ss[threadIdx.x] + ss[threadIdx.x + 64] + ss[threadIdx.x + 128] + ss[threadIdx.x + 192];
        q = sq[threadIdx.x] + sq[threadIdx.x + 64] + sq[threadIdx.x + 128] + sq[threadIdx.x + 192];
        atomicAdd(&g_sum[d], s);
        atomicAdd(&g_sumsq[d], q);
    }
}

__global__ void k_bnprep(const float* __restrict__ gamma,
                         const float* __restrict__ beta) {
    int d = threadIdx.x;
    if (d >= D) return;
    double mean = g_sum[d] / (double)NNODES;
    double var  = g_sumsq[d] / (double)NNODES - mean * mean;
    double inv  = 1.0 / sqrt(var + 1e-5);
    double sc   = (double)gamma[d] * inv;
    g_scale[d] = (float)sc;
    g_shift[d] = (float)((double)beta[d] - mean * sc);
}

// ---------------------------------------------------------------------------
// 7. BN apply -> output
// ---------------------------------------------------------------------------
__global__ void __launch_bounds__(256) k_fin(float* __restrict__ out) {
    int i = blockIdx.x * blockDim.x + threadIdx.x;  // float4 index
    if (i >= NNODES * 16) return;
    float4 v = ((const float4*)g_x)[i];
    int d = (i & 15) * 4;
    v.x = v.x * g_scale[d + 0] + g_shift[d + 0];
    v.y = v.y * g_scale[d + 1] + g_shift[d + 1];
    v.z = v.z * g_scale[d + 2] + g_shift[d + 2];
    v.w = v.w * g_scale[d + 3] + g_shift[d + 3];
    ((float4*)out)[i] = v;
}

// ---------------------------------------------------------------------------
// Launch
// ---------------------------------------------------------------------------
extern "C" void kernel_launch(void* const* d_in, const int* in_sizes, int n_in,
                              void* d_out, int out_size) {
    const float* x     = (const float*)d_in[0];
    const void*  ei    = d_in[1];
    const float* Ws    = (const float*)d_in[2];
    const float* bs    = (const float*)d_in[3];
    const float* gamma = (const float*)d_in[4];
    const float* beta  = (const float*)d_in[5];
    float* out = (float*)d_out;

    k_zero<<<(NNODES + 255) / 256, 256>>>();
    k_detect<<<1, 256>>>((const int*)ei);
    k_hist<<<2048, 256>>>(ei);
    k_scan<<<1, 1024>>>();
    k_fill<<<2048, 256>>>(ei);

    int gemm_blocks = (NNODES + 127) / 128;       // 782
    int agg_blocks  = (NNODES * 32 + 255) / 256;  // 12500

    for (int L = 0; L < 3; L++) {
        const float* Xin = (L == 0) ? x : nullptr;  // nullptr => use g_x
        k_gemm<<<gemm_blocks, 256>>>(Xin, Ws + L * 64 * 64);
        k_agg<<<agg_blocks, 256>>>(bs + L * 64);
    }

    k_bnred<<<512, 256>>>();
    k_bnprep<<<1, 64>>>(gamma, beta);
    k_fin<<<(NNODES * 16 + 255) / 256, 256>>>(out);
}

// round 2
// speedup vs baseline: 1.6086x; 1.6086x over previous
#include <cuda_runtime.h>

// Problem constants
constexpr int NNODES = 100000;   // N_USERS + N_ITEMS
constexpr int D      = 64;       // DIM
constexpr int NE     = 1250000;  // N_EDGES
constexpr int SB     = (NNODES + 1023) / 1024;  // 98 scan blocks

// ---------------------------------------------------------------------------
// Device scratch
// ---------------------------------------------------------------------------
__device__ float  g_h[NNODES * D];
__device__ float  g_x[NNODES * D];
__device__ float  g_dis[NNODES];
__device__ int    g_cnt[NNODES];
__device__ int    g_rowptr[NNODES + 1];
__device__ int    g_cursor[NNODES];
__device__ int    g_colidx[NE];
__device__ int    g_blocksum[SB];
__device__ int    g_blockoff[SB];
__device__ double g_sum[D];
__device__ double g_sumsq[D];
__device__ float  g_scale[D];
__device__ float  g_shift[D];
__device__ int    g_is64;

// ---------------------------------------------------------------------------
// 0. zero counters / BN accumulators
// ---------------------------------------------------------------------------
__global__ void k_zero() {
    int i = blockIdx.x * blockDim.x + threadIdx.x;
    if (i < NNODES) g_cnt[i] = 0;
    if (i < D) { g_sum[i] = 0.0; g_sumsq[i] = 0.0; }
}

// ---------------------------------------------------------------------------
// 0b. detect edge_index dtype
// ---------------------------------------------------------------------------
__global__ void k_detect(const int* __restrict__ e) {
    __shared__ int s_nz;
    if (threadIdx.x == 0) s_nz = 0;
    __syncthreads();
    int nz = 0;
    for (int i = threadIdx.x; i < 2048; i += blockDim.x)
        nz |= (e[2 * i + 1] != 0);
    if (nz) atomicOr(&s_nz, 1);
    __syncthreads();
    if (threadIdx.x == 0) g_is64 = (s_nz == 0) ? 1 : 0;
}

// ---------------------------------------------------------------------------
// 1. histogram of dst
// ---------------------------------------------------------------------------
__global__ void k_hist(const void* __restrict__ ep) {
    int i0 = blockIdx.x * blockDim.x + threadIdx.x;
    int stride = gridDim.x * blockDim.x;
    if (g_is64) {
        const long long* e = (const long long*)ep;
        for (int i = i0; i < NE; i += stride)
            atomicAdd(&g_cnt[(int)e[NE + i]], 1);
    } else {
        const int* e = (const int*)ep;
        for (int i = i0; i < NE; i += stride)
            atomicAdd(&g_cnt[e[NE + i]], 1);
    }
}

// ---------------------------------------------------------------------------
// 2. Parallel exclusive scan: 98 blocks x 1024 elems (256 thr x 4) ->
//    local prefixes + block sums; scan block sums; add offsets + dis/cursor.
// ---------------------------------------------------------------------------
__global__ void __launch_bounds__(256) k_scan1() {
    __shared__ int warpsum[8];
    int b = blockIdx.x;
    int t = threadIdx.x;
    int base = b * 1024 + t * 4;
    int c[4];
    int s = 0;
#pragma unroll
    for (int i = 0; i < 4; i++) {
        int idx = base + i;
        c[i] = (idx < NNODES) ? g_cnt[idx] : 0;
        s += c[i];
    }
    int lane = t & 31, w = t >> 5;
    int v = s;
#pragma unroll
    for (int off = 1; off < 32; off <<= 1) {
        int u = __shfl_up_sync(~0u, v, off);
        if (lane >= off) v += u;
    }
    if (lane == 31) warpsum[w] = v;
    __syncthreads();
    if (t < 8) {
        int u = warpsum[t];
#pragma unroll
        for (int off = 1; off < 8; off <<= 1) {
            int uu = __shfl_up_sync(0xffu, u, off);
            if (t >= off) u += uu;
        }
        warpsum[t] = u;
    }
    __syncthreads();
    int excl = v - s + (w > 0 ? warpsum[w - 1] : 0);
    int run = excl;
#pragma unroll
    for (int i = 0; i < 4; i++) {
        int idx = base + i;
        if (idx < NNODES) g_rowptr[idx] = run;
        run += c[i];
    }
    if (t == 255) g_blocksum[b] = warpsum[7];
}

__global__ void __launch_bounds__(128) k_scan2() {
    __shared__ int sm[128];
    int t = threadIdx.x;
    int v = (t < SB) ? g_blocksum[t] : 0;
    sm[t] = v;
    __syncthreads();
    for (int off = 1; off < 128; off <<= 1) {
        int u = (t >= off) ? sm[t - off] : 0;
        __syncthreads();
        sm[t] += u;
        __syncthreads();
    }
    if (t < SB) g_blockoff[t] = sm[t] - v;   // exclusive
    if (t == SB - 1) g_rowptr[NNODES] = sm[t];
}

__global__ void __launch_bounds__(256) k_scan3() {
    int b = blockIdx.x;
    int t = threadIdx.x;
    int off = g_blockoff[b];
    int base = b * 1024 + t * 4;
#pragma unroll
    for (int i = 0; i < 4; i++) {
        int idx = base + i;
        if (idx < NNODES) {
            int r = g_rowptr[idx] + off;
            g_rowptr[idx] = r;
            g_cursor[idx] = r;
            g_dis[idx] = rsqrtf((float)(g_cnt[idx] + 1));
        }
    }
}

// ---------------------------------------------------------------------------
// 3. CSR fill
// ---------------------------------------------------------------------------
__global__ void k_fill(const void* __restrict__ ep) {
    int i0 = blockIdx.x * blockDim.x + threadIdx.x;
    int stride = gridDim.x * blockDim.x;
    if (g_is64) {
        const long long* e = (const long long*)ep;
        for (int i = i0; i < NE; i += stride) {
            int src = (int)e[i];
            int dst = (int)e[NE + i];
            int p = atomicAdd(&g_cursor[dst], 1);
            g_colidx[p] = src;
        }
    } else {
        const int* e = (const int*)ep;
        for (int i = i0; i < NE; i += stride) {
            int src = e[i];
            int dst = e[NE + i];
            int p = atomicAdd(&g_cursor[dst], 1);
            g_colidx[p] = src;
        }
    }
}

// ---------------------------------------------------------------------------
// 4. GEMM + scale epilogue:  g_h[n] = dis[n] * (X[n] @ W^T)
// ---------------------------------------------------------------------------
__global__ void __launch_bounds__(256) k_gemm(const float* __restrict__ Xin,
                                              const float* __restrict__ W) {
    __shared__ float sx[128 * 64];
    __shared__ float sw[64 * 64];
    const float* X = Xin ? Xin : g_x;
    int tid = threadIdx.x;

    for (int i = tid; i < 4096; i += 256) {
        int d = i >> 6, k = i & 63;
        sw[k * 64 + d] = W[i];
    }
    int n0 = blockIdx.x * 128;
    const float4* X4 = (const float4*)X;
    float4* sx4 = (float4*)sx;
    for (int i = tid; i < 2048; i += 256) {
        int n = n0 + (i >> 4);
        sx4[i] = (n < NNODES) ? X4[(size_t)n * 16 + (i & 15)]
                              : make_float4(0.f, 0.f, 0.f, 0.f);
    }
    __syncthreads();

    int tc = tid & 7, tr = tid >> 3;
    int d0 = tc * 8;
    int nb = tr * 4;
    float acc[4][8];
#pragma unroll
    for (int i = 0; i < 4; i++)
#pragma unroll
        for (int j = 0; j < 8; j++) acc[i][j] = 0.f;

#pragma unroll 8
    for (int k = 0; k < 64; k++) {
        float4 wa = *(const float4*)&sw[k * 64 + d0];
        float4 wb = *(const float4*)&sw[k * 64 + d0 + 4];
#pragma unroll
        for (int i = 0; i < 4; i++) {
            float xv = sx[(nb + i) * 64 + k];
            acc[i][0] += xv * wa.x; acc[i][1] += xv * wa.y;
            acc[i][2] += xv * wa.z; acc[i][3] += xv * wa.w;
            acc[i][4] += xv * wb.x; acc[i][5] += xv * wb.y;
            acc[i][6] += xv * wb.z; acc[i][7] += xv * wb.w;
        }
    }
#pragma unroll
    for (int i = 0; i < 4; i++) {
        int n = n0 + nb + i;
        if (n < NNODES) {
            float dv = g_dis[n];
            float4 o0 = make_float4(acc[i][0] * dv, acc[i][1] * dv,
                                    acc[i][2] * dv, acc[i][3] * dv);
            float4 o1 = make_float4(acc[i][4] * dv, acc[i][5] * dv,
                                    acc[i][6] * dv, acc[i][7] * dv);
            *(float4*)&g_h[(size_t)n * 64 + d0]     = o0;
            *(float4*)&g_h[(size_t)n * 64 + d0 + 4] = o1;
        }
    }
}

// ---------------------------------------------------------------------------
// 5. Aggregation: warp per node, lane l owns float2 at dim 2l.
// ---------------------------------------------------------------------------
__global__ void __launch_bounds__(256) k_agg(const float* __restrict__ b) {
    int w = (blockIdx.x * blockDim.x + threadIdx.x) >> 5;
    int l = threadIdx.x & 31;
    if (w >= NNODES) return;
    const float2* __restrict__ h2 = (const float2*)g_h;
    float2 acc = h2[(size_t)w * 32 + l];  // self loop
    int beg = g_rowptr[w];
    int end = g_rowptr[w + 1];
    int j = beg;
    for (; j + 3 < end; j += 4) {
        int s0 = g_colidx[j], s1 = g_colidx[j + 1];
        int s2 = g_colidx[j + 2], s3 = g_colidx[j + 3];
        float2 a0 = h2[(size_t)s0 * 32 + l];
        float2 a1 = h2[(size_t)s1 * 32 + l];
        float2 a2 = h2[(size_t)s2 * 32 + l];
        float2 a3 = h2[(size_t)s3 * 32 + l];
        acc.x += (a0.x + a1.x) + (a2.x + a3.x);
        acc.y += (a0.y + a1.y) + (a2.y + a3.y);
    }
    for (; j < end; j++) {
        int s = g_colidx[j];
        float2 a = h2[(size_t)s * 32 + l];
        acc.x += a.x; acc.y += a.y;
    }
    float dv = g_dis[w];
    float2 bv = ((const float2*)b)[l];
    float2 r;
    r.x = acc.x * dv + bv.x;
    r.y = acc.y * dv + bv.y;
    ((float2*)g_x)[(size_t)w * 32 + l] = r;
}

// ---------------------------------------------------------------------------
// 6. BN column reduction (double accumulators)
// ---------------------------------------------------------------------------
__global__ void __launch_bounds__(256) k_bnred() {
    int d  = threadIdx.x & 63;
    int r0 = blockIdx.x * 4 + (threadIdx.x >> 6);
    int rs = gridDim.x * 4;
    double s = 0.0, q = 0.0;
    for (int n = r0; n < NNODES; n += rs) {
        double v = (double)g_x[(size_t)n * 64 + d];
        s += v;
        q += v * v;
    }
    __shared__ double ss[256], sq[256];
    ss[threadIdx.x] = s;
    sq[threadIdx.x] = q;
    __syncthreads();
    if (threadIdx.x < 64) {
        s = ss[threadIdx.x] + ss[threadIdx.x + 64] + ss[threadIdx.x + 128] + ss[threadIdx.x + 192];
        q = sq[threadIdx.x] + sq[threadIdx.x + 64] + sq[threadIdx.x + 128] + sq[threadIdx.x + 192];
        atomicAdd(&g_sum[d], s);
        atomicAdd(&g_sumsq[d], q);
    }
}

__global__ void k_bnprep(const float* __restrict__ gamma,
                         const float* __restrict__ beta) {
    int d = threadIdx.x;
    if (d >= D) return;
    double mean = g_sum[d] / (double)NNODES;
    double var  = g_sumsq[d] / (double)NNODES - mean * mean;
    double inv  = 1.0 / sqrt(var + 1e-5);
    double sc   = (double)gamma[d] * inv;
    g_scale[d] = (float)sc;
    g_shift[d] = (float)((double)beta[d] - mean * sc);
}

// ---------------------------------------------------------------------------
// 7. BN apply -> output
// ---------------------------------------------------------------------------
__global__ void __launch_bounds__(256) k_fin(float* __restrict__ out) {
    int i = blockIdx.x * blockDim.x + threadIdx.x;
    if (i >= NNODES * 16) return;
    float4 v = ((const float4*)g_x)[i];
    int d = (i & 15) * 4;
    v.x = v.x * g_scale[d + 0] + g_shift[d + 0];
    v.y = v.y * g_scale[d + 1] + g_shift[d + 1];
    v.z = v.z * g_scale[d + 2] + g_shift[d + 2];
    v.w = v.w * g_scale[d + 3] + g_shift[d + 3];
    ((float4*)out)[i] = v;
}

// ---------------------------------------------------------------------------
// Launch
// ---------------------------------------------------------------------------
extern "C" void kernel_launch(void* const* d_in, const int* in_sizes, int n_in,
                              void* d_out, int out_size) {
    const float* x     = (const float*)d_in[0];
    const void*  ei    = d_in[1];
    const float* Ws    = (const float*)d_in[2];
    const float* bs    = (const float*)d_in[3];
    const float* gamma = (const float*)d_in[4];
    const float* beta  = (const float*)d_in[5];
    float* out = (float*)d_out;

    k_zero<<<(NNODES + 255) / 256, 256>>>();
    k_detect<<<1, 256>>>((const int*)ei);
    k_hist<<<2048, 256>>>(ei);
    k_scan1<<<SB, 256>>>();
    k_scan2<<<1, 128>>>();
    k_scan3<<<SB, 256>>>();
    k_fill<<<2048, 256>>>(ei);

    int gemm_blocks = (NNODES + 127) / 128;
    int agg_blocks  = (NNODES * 32 + 255) / 256;

    for (int L = 0; L < 3; L++) {
        const float* Xin = (L == 0) ? x : nullptr;
        k_gemm<<<gemm_blocks, 256>>>(Xin, Ws + L * 64 * 64);
        k_agg<<<agg_blocks, 256>>>(bs + L * 64);
    }

    k_bnred<<<512, 256>>>();
    k_bnprep<<<1, 64>>>(gamma, beta);
    k_fin<<<(NNODES * 16 + 255) / 256, 256>>>(out);
}